// round 2
// baseline (speedup 1.0000x reference)
#include <cuda_runtime.h>
#include <math.h>

#define N_NODES 100000
#define N_EDGES 1600000
#define NFEAT   512
#define NHID    128
#define NCLASS  40

// ---------------- scratch (static __device__, no allocs) ----------------
__device__ float g_H1[(size_t)N_NODES * NHID];    // X @ W1
__device__ float g_H [(size_t)N_NODES * NHID];    // relu(A@H1 + b1)
__device__ float g_S2[(size_t)N_NODES * NCLASS];  // H @ W2
__device__ int   g_rowptr[N_NODES + 1];
__device__ int   g_fill[N_NODES];                 // counts, then running offsets
__device__ int   g_cols[N_EDGES];
__device__ float g_vals[N_EDGES];
__device__ int   g_is64;                          // 1 if adj indices are int64

// ---------------- dtype detection (int64 vs int32 indices) ----------------
// If buffer is int64 (values < 2^31), every odd 32-bit word is 0.
__global__ void k_detect(const int* __restrict__ rowi) {
    __shared__ int red[256];
    int acc = 0;
    for (int i = threadIdx.x; i < 1024; i += 256) acc |= rowi[2 * i + 1];
    red[threadIdx.x] = acc;
    __syncthreads();
    for (int s = 128; s > 0; s >>= 1) {
        if (threadIdx.x < s) red[threadIdx.x] |= red[threadIdx.x + s];
        __syncthreads();
    }
    if (threadIdx.x == 0) g_is64 = (red[0] == 0) ? 1 : 0;
}

__device__ __forceinline__ int load_idx(const void* p, int e, int is64) {
    return is64 ? (int)((const long long*)p)[e] : ((const int*)p)[e];
}

// ---------------- CSR build ----------------
__global__ void k_zero_counts() {
    int i = blockIdx.x * blockDim.x + threadIdx.x;
    if (i < N_NODES) g_fill[i] = 0;
}

__global__ void k_hist(const void* __restrict__ row) {
    int e = blockIdx.x * blockDim.x + threadIdx.x;
    if (e < N_EDGES) {
        int r = load_idx(row, e, g_is64);
        atomicAdd(&g_fill[r], 1);
    }
}

// single-block chunked exclusive scan of g_fill -> g_rowptr (g_fill = start offsets)
__global__ void k_scan() {
    __shared__ int sdata[1024];
    int tid = threadIdx.x;
    int carry = 0;
    for (int base = 0; base < N_NODES; base += 1024) {
        __syncthreads();
        int i = base + tid;
        int v = (i < N_NODES) ? g_fill[i] : 0;
        sdata[tid] = v;
        __syncthreads();
        #pragma unroll
        for (int off = 1; off < 1024; off <<= 1) {
            int t = (tid >= off) ? sdata[tid - off] : 0;
            __syncthreads();
            sdata[tid] += t;
            __syncthreads();
        }
        int incl = sdata[tid];
        int excl = incl - v;
        if (i < N_NODES) {
            int st = carry + excl;
            g_rowptr[i] = st;
            g_fill[i]   = st;
        }
        carry += sdata[1023];
    }
    if (tid == 0) g_rowptr[N_NODES] = carry;
}

__global__ void k_scatter(const void* __restrict__ row,
                          const void* __restrict__ col,
                          const float* __restrict__ val) {
    int e = blockIdx.x * blockDim.x + threadIdx.x;
    if (e < N_EDGES) {
        int is64 = g_is64;
        int r = load_idx(row, e, is64);
        int c = load_idx(col, e, is64);
        int pos = atomicAdd(&g_fill[r], 1);
        g_cols[pos] = c;
        g_vals[pos] = val[e];
    }
}

// ---------------- GEMM1: [100000,512] x [512,128] -> g_H1 ----------------
// BM=128 BN=128 BK=16, 256 threads, 8x8 per-thread tile
__global__ __launch_bounds__(256) void k_gemm1(const float* __restrict__ A,
                                               const float* __restrict__ B) {
    __shared__ float As[16][128];  // transposed: As[k][m]
    __shared__ float Bs[16][128];  // Bs[k][n]

    const int block_row = blockIdx.x * 128;
    const int tid = threadIdx.x;

    const int a_row = tid >> 2;        // 0..63
    const int a_c4  = tid & 3;         // float4 idx in K (16 floats -> 4 float4)
    const int b_k   = tid >> 5;        // 0..7
    const int b_c4  = tid & 31;        // float4 idx in N (128 floats -> 32 float4)

    const int tx = tid & 15;
    const int ty = tid >> 4;

    float acc[8][8];
    #pragma unroll
    for (int i = 0; i < 8; i++)
        #pragma unroll
        for (int j = 0; j < 8; j++) acc[i][j] = 0.f;

    for (int k0 = 0; k0 < NFEAT; k0 += 16) {
        #pragma unroll
        for (int r = 0; r < 2; r++) {
            int m = a_row + 64 * r;
            int grow = block_row + m;
            float4 v = make_float4(0.f, 0.f, 0.f, 0.f);
            if (grow < N_NODES)
                v = reinterpret_cast<const float4*>(A + (size_t)grow * NFEAT + k0)[a_c4];
            As[a_c4 * 4 + 0][m] = v.x;
            As[a_c4 * 4 + 1][m] = v.y;
            As[a_c4 * 4 + 2][m] = v.z;
            As[a_c4 * 4 + 3][m] = v.w;
        }
        #pragma unroll
        for (int r = 0; r < 2; r++) {
            int kk = b_k + 8 * r;
            float4 v = reinterpret_cast<const float4*>(B + (size_t)(k0 + kk) * NHID)[b_c4];
            reinterpret_cast<float4*>(&Bs[kk][b_c4 * 4])[0] = v;
        }
        __syncthreads();

        #pragma unroll
        for (int k = 0; k < 16; k++) {
            float ar[8], br[8];
            float4 a0 = *reinterpret_cast<const float4*>(&As[k][ty * 8]);
            float4 a1 = *reinterpret_cast<const float4*>(&As[k][ty * 8 + 4]);
            float4 b0 = *reinterpret_cast<const float4*>(&Bs[k][tx * 8]);
            float4 b1 = *reinterpret_cast<const float4*>(&Bs[k][tx * 8 + 4]);
            ar[0]=a0.x; ar[1]=a0.y; ar[2]=a0.z; ar[3]=a0.w;
            ar[4]=a1.x; ar[5]=a1.y; ar[6]=a1.z; ar[7]=a1.w;
            br[0]=b0.x; br[1]=b0.y; br[2]=b0.z; br[3]=b0.w;
            br[4]=b1.x; br[5]=b1.y; br[6]=b1.z; br[7]=b1.w;
            #pragma unroll
            for (int i = 0; i < 8; i++)
                #pragma unroll
                for (int j = 0; j < 8; j++)
                    acc[i][j] = fmaf(ar[i], br[j], acc[i][j]);
        }
        __syncthreads();
    }

    #pragma unroll
    for (int i = 0; i < 8; i++) {
        int grow = block_row + ty * 8 + i;
        if (grow < N_NODES) {
            float* crow = g_H1 + (size_t)grow * NHID + tx * 8;
            reinterpret_cast<float4*>(crow)[0] = make_float4(acc[i][0], acc[i][1], acc[i][2], acc[i][3]);
            reinterpret_cast<float4*>(crow)[1] = make_float4(acc[i][4], acc[i][5], acc[i][6], acc[i][7]);
        }
    }
}

// ---------------- SpMM (CSR gather, 1 warp/row) ----------------
// LAYER 1: out = relu(A @ g_H1 + b1) -> g_H     (F = NHID)
// LAYER 2: out = A @ g_S2 + b2       -> d_out   (F = NCLASS)
template <int LAYER>
__global__ void k_spmm(const float* __restrict__ bias, float* __restrict__ out_p) {
    constexpr int F = (LAYER == 1) ? NHID : NCLASS;
    constexpr int NV = (F + 31) / 32;
    int gw = (blockIdx.x * blockDim.x + threadIdx.x) >> 5;
    int lane = threadIdx.x & 31;
    if (gw >= N_NODES) return;

    const float* dense = (LAYER == 1) ? g_H1 : g_S2;
    float* out = (LAYER == 1) ? g_H : out_p;

    int s = g_rowptr[gw];
    int e = g_rowptr[gw + 1];
    float acc[NV];
    #pragma unroll
    for (int j = 0; j < NV; j++) acc[j] = 0.f;

    for (int i = s; i < e; i++) {
        int c = g_cols[i];
        float v = g_vals[i];
        const float* dr = dense + (size_t)c * F;
        #pragma unroll
        for (int j = 0; j < NV; j++) {
            int col = lane + j * 32;
            if ((F % 32 == 0) || col < F) acc[j] += v * dr[col];
        }
    }
    #pragma unroll
    for (int j = 0; j < NV; j++) {
        int col = lane + j * 32;
        if ((F % 32 == 0) || col < F) {
            float r = acc[j] + bias[col];
            out[(size_t)gw * F + col] = (LAYER == 1) ? fmaxf(r, 0.f) : r;
        }
    }
}

// ---------------- GEMM2: [100000,128] x [128,40] -> g_S2 ----------------
__global__ __launch_bounds__(256) void k_gemm2(const float* __restrict__ W2) {
    __shared__ float W2s[NHID * NCLASS];  // 20KB
    __shared__ float Hs[32][NHID];        // 16KB
    int tid = threadIdx.x;
    int rows0 = blockIdx.x * 32;

    for (int i = tid; i < NHID * NCLASS; i += 256) W2s[i] = W2[i];
    for (int i = tid; i < 32 * NHID; i += 256) {
        int r = i >> 7, k = i & 127;
        int grow = rows0 + r;
        Hs[r][k] = (grow < N_NODES) ? g_H[(size_t)grow * NHID + k] : 0.f;
    }
    __syncthreads();

    for (int idx = tid; idx < 32 * NCLASS; idx += 256) {
        int r = idx / NCLASS;
        int c = idx % NCLASS;
        int grow = rows0 + r;
        if (grow >= N_NODES) continue;
        float acc = 0.f;
        #pragma unroll
        for (int k = 0; k < NHID; k++)
            acc = fmaf(Hs[r][k], W2s[k * NCLASS + c], acc);
        g_S2[(size_t)grow * NCLASS + c] = acc;
    }
}

// ---------------- log_softmax over 40 classes, 1 warp/row, in-place ----------------
__global__ void k_logsoftmax(float* __restrict__ out) {
    int row = (blockIdx.x * blockDim.x + threadIdx.x) >> 5;
    int lane = threadIdx.x & 31;
    if (row >= N_NODES) return;
    float* p = out + (size_t)row * NCLASS;
    float v0 = p[lane];
    float v1 = (lane < NCLASS - 32) ? p[lane + 32] : -INFINITY;
    float m = fmaxf(v0, v1);
    #pragma unroll
    for (int off = 16; off > 0; off >>= 1)
        m = fmaxf(m, __shfl_xor_sync(0xFFFFFFFF, m, off));
    float s = expf(v0 - m) + ((lane < NCLASS - 32) ? expf(v1 - m) : 0.f);
    #pragma unroll
    for (int off = 16; off > 0; off >>= 1)
        s += __shfl_xor_sync(0xFFFFFFFF, s, off);
    float lse = m + logf(s);
    p[lane] = v0 - lse;
    if (lane < NCLASS - 32) p[lane + 32] = v1 - lse;
}

// ---------------- launch ----------------
extern "C" void kernel_launch(void* const* d_in, const int* in_sizes, int n_in,
                              void* d_out, int out_size) {
    const float* x    = (const float*)d_in[0];
    const void*  arow = d_in[1];
    const void*  acol = d_in[2];
    const float* aval = (const float*)d_in[3];
    const float* W1   = (const float*)d_in[4];
    const float* b1   = (const float*)d_in[5];
    const float* W2   = (const float*)d_in[6];
    const float* b2   = (const float*)d_in[7];
    float* out = (float*)d_out;

    // detect index dtype (int32 vs int64), then CSR build
    k_detect<<<1, 256>>>((const int*)arow);
    k_zero_counts<<<(N_NODES + 255) / 256, 256>>>();
    k_hist<<<(N_EDGES + 255) / 256, 256>>>(arow);
    k_scan<<<1, 1024>>>();
    k_scatter<<<(N_EDGES + 255) / 256, 256>>>(arow, acol, aval);

    // layer 1
    k_gemm1<<<(N_NODES + 127) / 128, 256>>>(x, W1);
    k_spmm<1><<<(N_NODES * 32 + 255) / 256, 256>>>(b1, nullptr);

    // layer 2
    k_gemm2<<<(N_NODES + 31) / 32, 256>>>(W2);
    k_spmm<2><<<(N_NODES * 32 + 255) / 256, 256>>>(b2, out);

    // log_softmax in place on d_out
    k_logsoftmax<<<(N_NODES * 32 + 255) / 256, 256>>>(out);
}

// round 3
// speedup vs baseline: 1.7859x; 1.7859x over previous
#include <cuda_runtime.h>
#include <math.h>
#include <stdint.h>

#define N_NODES 100000
#define N_EDGES 1600000
#define NFEAT   512
#define NHID    128
#define NCLASS  40

#define SCAN_BLK   1024
#define SCAN_NBLK  ((N_NODES + SCAN_BLK - 1) / SCAN_BLK)   // 98

// ---------------- scratch (static __device__, no allocs) ----------------
__device__ float g_H1[(size_t)N_NODES * NHID];    // X @ W1
__device__ float g_H [(size_t)N_NODES * NHID];    // relu(A@H1 + b1)
__device__ float g_S2[(size_t)N_NODES * NCLASS];  // H @ W2
__device__ int   g_rowptr[N_NODES + 1];
__device__ int   g_fill[N_NODES];                 // counts -> running offsets
__device__ int   g_cols[N_EDGES];
__device__ float g_vals[N_EDGES];
__device__ int   g_bsum[SCAN_NBLK];
__device__ int   g_is64;                          // 1 if adj indices are int64

// ---------------- dtype detection (int64 vs int32 indices) ----------------
__global__ void k_detect(const int* __restrict__ rowi) {
    __shared__ int red[256];
    int acc = 0;
    for (int i = threadIdx.x; i < 1024; i += 256) acc |= rowi[2 * i + 1];
    red[threadIdx.x] = acc;
    __syncthreads();
    for (int s = 128; s > 0; s >>= 1) {
        if (threadIdx.x < s) red[threadIdx.x] |= red[threadIdx.x + s];
        __syncthreads();
    }
    if (threadIdx.x == 0) g_is64 = (red[0] == 0) ? 1 : 0;
}

__device__ __forceinline__ int load_idx(const void* p, int e, int is64) {
    return is64 ? (int)((const long long*)p)[e] : ((const int*)p)[e];
}

// ---------------- CSR build ----------------
__global__ void k_zero_counts() {
    int i = blockIdx.x * blockDim.x + threadIdx.x;
    if (i < N_NODES) g_fill[i] = 0;
}

__global__ void k_hist(const void* __restrict__ row) {
    int e = blockIdx.x * blockDim.x + threadIdx.x;
    if (e < N_EDGES) atomicAdd(&g_fill[load_idx(row, e, g_is64)], 1);
}

// phase 1: per-block inclusive scan (warp shuffles), local exclusive to rowptr,
// block total to g_bsum
__global__ __launch_bounds__(SCAN_BLK) void k_scan1() {
    __shared__ int wsum[32];
    int tid = threadIdx.x;
    int lane = tid & 31, warp = tid >> 5;
    int i = blockIdx.x * SCAN_BLK + tid;
    int v = (i < N_NODES) ? g_fill[i] : 0;

    int incl = v;
    #pragma unroll
    for (int off = 1; off < 32; off <<= 1) {
        int t = __shfl_up_sync(0xFFFFFFFF, incl, off);
        if (lane >= off) incl += t;
    }
    if (lane == 31) wsum[warp] = incl;
    __syncthreads();
    if (warp == 0) {
        int w = (lane < 32) ? wsum[lane] : 0;
        #pragma unroll
        for (int off = 1; off < 32; off <<= 1) {
            int t = __shfl_up_sync(0xFFFFFFFF, w, off);
            if (lane >= off) w += t;
        }
        wsum[lane] = w;
    }
    __syncthreads();
    int base = (warp > 0) ? wsum[warp - 1] : 0;
    int excl = base + incl - v;
    if (i < N_NODES) g_rowptr[i] = excl;
    if (tid == SCAN_BLK - 1) g_bsum[blockIdx.x] = base + incl;
}

// phase 2: exclusive scan of the 98 block sums (one block)
__global__ void k_scan2() {
    __shared__ int s[128];
    int tid = threadIdx.x;
    int v = (tid < SCAN_NBLK) ? g_bsum[tid] : 0;
    s[tid] = v;
    __syncthreads();
    for (int off = 1; off < 128; off <<= 1) {
        int t = (tid >= off) ? s[tid - off] : 0;
        __syncthreads();
        s[tid] += t;
        __syncthreads();
    }
    if (tid < SCAN_NBLK) g_bsum[tid] = s[tid] - v;  // exclusive
}

// phase 3: add block offsets; copy to g_fill; set rowptr[N]
__global__ void k_scan3() {
    int i = blockIdx.x * blockDim.x + threadIdx.x;
    if (i < N_NODES) {
        int v = g_rowptr[i] + g_bsum[i >> 10];
        g_rowptr[i] = v;
        g_fill[i]   = v;
    }
    if (i == 0) g_rowptr[N_NODES] = N_EDGES;
}

__global__ void k_scatter(const void* __restrict__ row,
                          const void* __restrict__ col,
                          const float* __restrict__ val) {
    int e = blockIdx.x * blockDim.x + threadIdx.x;
    if (e < N_EDGES) {
        int is64 = g_is64;
        int r = load_idx(row, e, is64);
        int c = load_idx(col, e, is64);
        int pos = atomicAdd(&g_fill[r], 1);
        g_cols[pos] = c;
        g_vals[pos] = val[e];
    }
}

// ---------------- GEMM1 (tf32 mma.sync): [100000,512]x[512,128] -> g_H1 ----
#define BM 128
#define BN 128
#define BK 32
#define AS_STRIDE 36    // conflict-free for a-frag pattern
#define BS_STRIDE 136   // conflict-free for b-frag pattern

__device__ __forceinline__ uint32_t f2tf32(float f) {
    uint32_t u;
    asm("cvt.rna.tf32.f32 %0, %1;" : "=r"(u) : "f"(f));
    return u;
}

__device__ __forceinline__ void mma_tf32(float c[4], uint32_t a0, uint32_t a1,
                                         uint32_t a2, uint32_t a3,
                                         uint32_t b0, uint32_t b1) {
    asm volatile(
        "mma.sync.aligned.m16n8k8.row.col.f32.tf32.tf32.f32 "
        "{%0,%1,%2,%3}, {%4,%5,%6,%7}, {%8,%9}, {%0,%1,%2,%3};\n"
        : "+f"(c[0]), "+f"(c[1]), "+f"(c[2]), "+f"(c[3])
        : "r"(a0), "r"(a1), "r"(a2), "r"(a3), "r"(b0), "r"(b1));
}

__global__ __launch_bounds__(256) void k_gemm1(const float* __restrict__ A,
                                               const float* __restrict__ B) {
    __shared__ uint32_t As[BM * AS_STRIDE];  // [m][k]
    __shared__ uint32_t Bs[BK * BS_STRIDE];  // [k][n]

    const int tid = threadIdx.x;
    const int lane = tid & 31;
    const int wid = tid >> 5;
    const int warp_m = wid >> 1;       // 0..3 (32 rows each)
    const int warp_n = wid & 1;        // 0..1 (64 cols each)
    const int block_row = blockIdx.x * BM;
    const int lq = lane >> 2;          // 0..7
    const int lr = lane & 3;           // 0..3

    float acc[2][8][4];
    #pragma unroll
    for (int i = 0; i < 2; i++)
        #pragma unroll
        for (int j = 0; j < 8; j++)
            #pragma unroll
            for (int r = 0; r < 4; r++) acc[i][j][r] = 0.f;

    for (int k0 = 0; k0 < NFEAT; k0 += BK) {
        // A tile: 128 rows x 32 cols = 1024 float4, 4 per thread
        #pragma unroll
        for (int r = 0; r < 4; r++) {
            int f = tid + r * 256;
            int m = f >> 3, c4 = f & 7;
            int grow = block_row + m;
            float4 v = make_float4(0.f, 0.f, 0.f, 0.f);
            if (grow < N_NODES)
                v = reinterpret_cast<const float4*>(A + (size_t)grow * NFEAT + k0)[c4];
            uint32_t* dst = &As[m * AS_STRIDE + c4 * 4];
            dst[0] = f2tf32(v.x); dst[1] = f2tf32(v.y);
            dst[2] = f2tf32(v.z); dst[3] = f2tf32(v.w);
        }
        // B tile: 32 rows x 128 cols = 1024 float4, 4 per thread
        #pragma unroll
        for (int r = 0; r < 4; r++) {
            int f = tid + r * 256;
            int kk = f >> 5, c4 = f & 31;
            float4 v = reinterpret_cast<const float4*>(B + (size_t)(k0 + kk) * NHID)[c4];
            uint32_t* dst = &Bs[kk * BS_STRIDE + c4 * 4];
            dst[0] = f2tf32(v.x); dst[1] = f2tf32(v.y);
            dst[2] = f2tf32(v.z); dst[3] = f2tf32(v.w);
        }
        __syncthreads();

        #pragma unroll
        for (int ks = 0; ks < 4; ks++) {
            int kb = ks * 8;
            uint32_t b0[8], b1[8];
            #pragma unroll
            for (int j = 0; j < 8; j++) {
                int n = warp_n * 64 + j * 8 + lq;
                b0[j] = Bs[(kb + lr) * BS_STRIDE + n];
                b1[j] = Bs[(kb + lr + 4) * BS_STRIDE + n];
            }
            #pragma unroll
            for (int i = 0; i < 2; i++) {
                int m = warp_m * 32 + i * 16 + lq;
                uint32_t a0 = As[m * AS_STRIDE + kb + lr];
                uint32_t a1 = As[(m + 8) * AS_STRIDE + kb + lr];
                uint32_t a2 = As[m * AS_STRIDE + kb + lr + 4];
                uint32_t a3 = As[(m + 8) * AS_STRIDE + kb + lr + 4];
                #pragma unroll
                for (int j = 0; j < 8; j++)
                    mma_tf32(acc[i][j], a0, a1, a2, a3, b0[j], b1[j]);
            }
        }
        __syncthreads();
    }

    // epilogue: c-frag (m16n8): c0/c1 at (lq, 2*lr), c2/c3 at (lq+8, 2*lr)
    #pragma unroll
    for (int i = 0; i < 2; i++) {
        int row0 = block_row + warp_m * 32 + i * 16 + lq;
        #pragma unroll
        for (int j = 0; j < 8; j++) {
            int col = warp_n * 64 + j * 8 + 2 * lr;
            if (row0 < N_NODES) {
                float2 v = make_float2(acc[i][j][0], acc[i][j][1]);
                *reinterpret_cast<float2*>(g_H1 + (size_t)row0 * NHID + col) = v;
            }
            if (row0 + 8 < N_NODES) {
                float2 v = make_float2(acc[i][j][2], acc[i][j][3]);
                *reinterpret_cast<float2*>(g_H1 + (size_t)(row0 + 8) * NHID + col) = v;
            }
        }
    }
}

// ---------------- SpMM (CSR gather, 1 warp/row) ----------------
template <int LAYER>
__global__ void k_spmm(const float* __restrict__ bias, float* __restrict__ out_p) {
    constexpr int F = (LAYER == 1) ? NHID : NCLASS;
    constexpr int NV = (F + 31) / 32;
    int gw = (blockIdx.x * blockDim.x + threadIdx.x) >> 5;
    int lane = threadIdx.x & 31;
    if (gw >= N_NODES) return;

    const float* dense = (LAYER == 1) ? g_H1 : g_S2;
    float* out = (LAYER == 1) ? g_H : out_p;

    int s = g_rowptr[gw];
    int e = g_rowptr[gw + 1];
    float acc[NV];
    #pragma unroll
    for (int j = 0; j < NV; j++) acc[j] = 0.f;

    for (int i = s; i < e; i++) {
        int c = g_cols[i];
        float v = g_vals[i];
        const float* dr = dense + (size_t)c * F;
        #pragma unroll
        for (int j = 0; j < NV; j++) {
            int col = lane + j * 32;
            if ((F % 32 == 0) || col < F) acc[j] += v * dr[col];
        }
    }
    #pragma unroll
    for (int j = 0; j < NV; j++) {
        int col = lane + j * 32;
        if ((F % 32 == 0) || col < F) {
            float r = acc[j] + bias[col];
            out[(size_t)gw * F + col] = (LAYER == 1) ? fmaxf(r, 0.f) : r;
        }
    }
}

// ---------------- GEMM2: [100000,128] x [128,40] -> g_S2 ----------------
__global__ __launch_bounds__(256) void k_gemm2(const float* __restrict__ W2) {
    __shared__ float W2s[NHID * NCLASS];  // 20KB
    __shared__ float Hs[32][NHID];        // 16KB
    int tid = threadIdx.x;
    int rows0 = blockIdx.x * 32;

    for (int i = tid; i < NHID * NCLASS; i += 256) W2s[i] = W2[i];
    for (int i = tid; i < 32 * NHID; i += 256) {
        int r = i >> 7, k = i & 127;
        int grow = rows0 + r;
        Hs[r][k] = (grow < N_NODES) ? g_H[(size_t)grow * NHID + k] : 0.f;
    }
    __syncthreads();

    for (int idx = tid; idx < 32 * NCLASS; idx += 256) {
        int r = idx / NCLASS;
        int c = idx % NCLASS;
        int grow = rows0 + r;
        if (grow >= N_NODES) continue;
        float acc = 0.f;
        #pragma unroll
        for (int k = 0; k < NHID; k++)
            acc = fmaf(Hs[r][k], W2s[k * NCLASS + c], acc);
        g_S2[(size_t)grow * NCLASS + c] = acc;
    }
}

// ---------------- log_softmax over 40 classes, 1 warp/row, in-place --------
__global__ void k_logsoftmax(float* __restrict__ out) {
    int row = (blockIdx.x * blockDim.x + threadIdx.x) >> 5;
    int lane = threadIdx.x & 31;
    if (row >= N_NODES) return;
    float* p = out + (size_t)row * NCLASS;
    float v0 = p[lane];
    float v1 = (lane < NCLASS - 32) ? p[lane + 32] : -INFINITY;
    float m = fmaxf(v0, v1);
    #pragma unroll
    for (int off = 16; off > 0; off >>= 1)
        m = fmaxf(m, __shfl_xor_sync(0xFFFFFFFF, m, off));
    float s = expf(v0 - m) + ((lane < NCLASS - 32) ? expf(v1 - m) : 0.f);
    #pragma unroll
    for (int off = 16; off > 0; off >>= 1)
        s += __shfl_xor_sync(0xFFFFFFFF, s, off);
    float lse = m + logf(s);
    p[lane] = v0 - lse;
    if (lane < NCLASS - 32) p[lane + 32] = v1 - lse;
}

// ---------------- launch ----------------
extern "C" void kernel_launch(void* const* d_in, const int* in_sizes, int n_in,
                              void* d_out, int out_size) {
    const float* x    = (const float*)d_in[0];
    const void*  arow = d_in[1];
    const void*  acol = d_in[2];
    const float* aval = (const float*)d_in[3];
    const float* W1   = (const float*)d_in[4];
    const float* b1   = (const float*)d_in[5];
    const float* W2   = (const float*)d_in[6];
    const float* b2   = (const float*)d_in[7];
    float* out = (float*)d_out;

    // CSR build
    k_detect<<<1, 256>>>((const int*)arow);
    k_zero_counts<<<(N_NODES + 255) / 256, 256>>>();
    k_hist<<<(N_EDGES + 255) / 256, 256>>>(arow);
    k_scan1<<<SCAN_NBLK, SCAN_BLK>>>();
    k_scan2<<<1, 128>>>();
    k_scan3<<<(N_NODES + 255) / 256, 256>>>();
    k_scatter<<<(N_EDGES + 255) / 256, 256>>>(arow, acol, aval);

    // layer 1
    k_gemm1<<<(N_NODES + BM - 1) / BM, 256>>>(x, W1);
    k_spmm<1><<<(N_NODES * 32 + 255) / 256, 256>>>(b1, nullptr);

    // layer 2
    k_gemm2<<<(N_NODES + 31) / 32, 256>>>(W2);
    k_spmm<2><<<(N_NODES * 32 + 255) / 256, 256>>>(b2, out);

    // log_softmax in place on d_out
    k_logsoftmax<<<(N_NODES * 32 + 255) / 256, 256>>>(out);
}

// round 4
// speedup vs baseline: 2.6642x; 1.4918x over previous
#include <cuda_runtime.h>
#include <math.h>
#include <stdint.h>

#define N_NODES 100000
#define N_EDGES 1600000
#define NFEAT   512
#define NHID    128
#define NCLASS  40

#define SCAN_BLK   1024
#define SCAN_NBLK  ((N_NODES + SCAN_BLK - 1) / SCAN_BLK)   // 98

// ---------------- scratch (static __device__, no allocs) ----------------
__device__ float g_H1[(size_t)N_NODES * NHID];    // X @ W1
__device__ float g_H [(size_t)N_NODES * NHID];    // relu(A@H1 + b1)
__device__ float g_S2[(size_t)N_NODES * NCLASS];  // H @ W2
__device__ int   g_rowptr[N_NODES + 1];
__device__ int   g_fill[N_NODES];                 // counts -> running offsets
__device__ int   g_cols[N_EDGES];
__device__ float g_vals[N_EDGES];
__device__ int   g_bsum[SCAN_NBLK];
__device__ int   g_is64;                          // 1 if adj indices are int64

// ---------------- dtype detection (int64 vs int32 indices) ----------------
__global__ void k_detect(const int* __restrict__ rowi) {
    __shared__ int red[256];
    int acc = 0;
    for (int i = threadIdx.x; i < 1024; i += 256) acc |= rowi[2 * i + 1];
    red[threadIdx.x] = acc;
    __syncthreads();
    for (int s = 128; s > 0; s >>= 1) {
        if (threadIdx.x < s) red[threadIdx.x] |= red[threadIdx.x + s];
        __syncthreads();
    }
    if (threadIdx.x == 0) g_is64 = (red[0] == 0) ? 1 : 0;
}

__device__ __forceinline__ int load_idx(const void* p, int e, int is64) {
    return is64 ? (int)((const long long*)p)[e] : ((const int*)p)[e];
}

// ---------------- CSR build ----------------
__global__ void k_zero_counts() {
    int i = blockIdx.x * blockDim.x + threadIdx.x;
    if (i < N_NODES) g_fill[i] = 0;
}

__global__ void k_hist(const void* __restrict__ row) {
    int e = blockIdx.x * blockDim.x + threadIdx.x;
    if (e < N_EDGES) atomicAdd(&g_fill[load_idx(row, e, g_is64)], 1);
}

__global__ __launch_bounds__(SCAN_BLK) void k_scan1() {
    __shared__ int wsum[32];
    int tid = threadIdx.x;
    int lane = tid & 31, warp = tid >> 5;
    int i = blockIdx.x * SCAN_BLK + tid;
    int v = (i < N_NODES) ? g_fill[i] : 0;

    int incl = v;
    #pragma unroll
    for (int off = 1; off < 32; off <<= 1) {
        int t = __shfl_up_sync(0xFFFFFFFF, incl, off);
        if (lane >= off) incl += t;
    }
    if (lane == 31) wsum[warp] = incl;
    __syncthreads();
    if (warp == 0) {
        int w = wsum[lane];
        #pragma unroll
        for (int off = 1; off < 32; off <<= 1) {
            int t = __shfl_up_sync(0xFFFFFFFF, w, off);
            if (lane >= off) w += t;
        }
        wsum[lane] = w;
    }
    __syncthreads();
    int base = (warp > 0) ? wsum[warp - 1] : 0;
    int excl = base + incl - v;
    if (i < N_NODES) g_rowptr[i] = excl;
    if (tid == SCAN_BLK - 1) g_bsum[blockIdx.x] = base + incl;
}

__global__ void k_scan2() {
    __shared__ int s[128];
    int tid = threadIdx.x;
    int v = (tid < SCAN_NBLK) ? g_bsum[tid] : 0;
    s[tid] = v;
    __syncthreads();
    for (int off = 1; off < 128; off <<= 1) {
        int t = (tid >= off) ? s[tid - off] : 0;
        __syncthreads();
        s[tid] += t;
        __syncthreads();
    }
    if (tid < SCAN_NBLK) g_bsum[tid] = s[tid] - v;  // exclusive
}

__global__ void k_scan3() {
    int i = blockIdx.x * blockDim.x + threadIdx.x;
    if (i < N_NODES) {
        int v = g_rowptr[i] + g_bsum[i >> 10];
        g_rowptr[i] = v;
        g_fill[i]   = v;
    }
    if (i == 0) g_rowptr[N_NODES] = N_EDGES;
}

__global__ void k_scatter(const void* __restrict__ row,
                          const void* __restrict__ col,
                          const float* __restrict__ val) {
    int e = blockIdx.x * blockDim.x + threadIdx.x;
    if (e < N_EDGES) {
        int is64 = g_is64;
        int r = load_idx(row, e, is64);
        int c = load_idx(col, e, is64);
        int pos = atomicAdd(&g_fill[r], 1);
        g_cols[pos] = c;
        g_vals[pos] = val[e];
    }
}

// ---------------- GEMM1 (tf32 mma.sync + cp.async double buffer) ----------
#define BM 128
#define BK 32
#define AS_STRIDE 36    // words; 144B rows, 16B aligned
#define BS_STRIDE 136   // words; 544B rows, 16B aligned
#define NIT (NFEAT / BK)

__device__ __forceinline__ void cp_async16(void* smem_dst, const void* gsrc, int src_bytes) {
    uint32_t saddr = (uint32_t)__cvta_generic_to_shared(smem_dst);
    asm volatile("cp.async.cg.shared.global [%0], [%1], 16, %2;\n"
                 :: "r"(saddr), "l"(gsrc), "r"(src_bytes));
}
#define CP_COMMIT() asm volatile("cp.async.commit_group;\n")
#define CP_WAIT(n)  asm volatile("cp.async.wait_group %0;\n" :: "n"(n))

__device__ __forceinline__ void mma_tf32(float c[4], uint32_t a0, uint32_t a1,
                                         uint32_t a2, uint32_t a3,
                                         uint32_t b0, uint32_t b1) {
    asm volatile(
        "mma.sync.aligned.m16n8k8.row.col.f32.tf32.tf32.f32 "
        "{%0,%1,%2,%3}, {%4,%5,%6,%7}, {%8,%9}, {%0,%1,%2,%3};\n"
        : "+f"(c[0]), "+f"(c[1]), "+f"(c[2]), "+f"(c[3])
        : "r"(a0), "r"(a1), "r"(a2), "r"(a3), "r"(b0), "r"(b1));
}

__global__ __launch_bounds__(256) void k_gemm1(const float* __restrict__ A,
                                               const float* __restrict__ B) {
    __shared__ float As[2][BM * AS_STRIDE];
    __shared__ float Bs[2][BK * BS_STRIDE];

    const int tid = threadIdx.x;
    const int lane = tid & 31;
    const int wid = tid >> 5;
    const int warp_m = wid >> 1;
    const int warp_n = wid & 1;
    const int block_row = blockIdx.x * BM;
    const int lq = lane >> 2;
    const int lr = lane & 3;

    float acc[2][8][4];
    #pragma unroll
    for (int i = 0; i < 2; i++)
        #pragma unroll
        for (int j = 0; j < 8; j++)
            #pragma unroll
            for (int r = 0; r < 4; r++) acc[i][j][r] = 0.f;

    // stage loader (raw fp32 bits; HW truncates to tf32 in the MMA)
    #define LOAD_STAGE(st, k0)                                                   \
    do {                                                                         \
        _Pragma("unroll")                                                        \
        for (int r = 0; r < 4; r++) {                                            \
            int f = tid + r * 256;                                               \
            int m = f >> 3, c4 = f & 7;                                          \
            int grow = block_row + m;                                            \
            int ok = grow < N_NODES;                                             \
            const float* src = A + (size_t)(ok ? grow : 0) * NFEAT + (k0) + c4 * 4; \
            cp_async16(&As[st][m * AS_STRIDE + c4 * 4], src, ok ? 16 : 0);       \
        }                                                                        \
        _Pragma("unroll")                                                        \
        for (int r = 0; r < 4; r++) {                                            \
            int f = tid + r * 256;                                               \
            int kk = f >> 5, c4 = f & 31;                                        \
            cp_async16(&Bs[st][kk * BS_STRIDE + c4 * 4],                         \
                       B + (size_t)((k0) + kk) * NHID + c4 * 4, 16);             \
        }                                                                        \
    } while (0)

    LOAD_STAGE(0, 0);
    CP_COMMIT();

    for (int it = 0; it < NIT; it++) {
        int st = it & 1;
        if (it + 1 < NIT) {
            LOAD_STAGE(st ^ 1, (it + 1) * BK);
            CP_COMMIT();
            CP_WAIT(1);
        } else {
            CP_WAIT(0);
        }
        __syncthreads();

        #pragma unroll
        for (int ks = 0; ks < 4; ks++) {
            int kb = ks * 8;
            uint32_t b0[8], b1[8];
            #pragma unroll
            for (int j = 0; j < 8; j++) {
                int n = warp_n * 64 + j * 8 + lq;
                b0[j] = __float_as_uint(Bs[st][(kb + lr) * BS_STRIDE + n]);
                b1[j] = __float_as_uint(Bs[st][(kb + lr + 4) * BS_STRIDE + n]);
            }
            #pragma unroll
            for (int i = 0; i < 2; i++) {
                int m = warp_m * 32 + i * 16 + lq;
                uint32_t a0 = __float_as_uint(As[st][m * AS_STRIDE + kb + lr]);
                uint32_t a1 = __float_as_uint(As[st][(m + 8) * AS_STRIDE + kb + lr]);
                uint32_t a2 = __float_as_uint(As[st][m * AS_STRIDE + kb + lr + 4]);
                uint32_t a3 = __float_as_uint(As[st][(m + 8) * AS_STRIDE + kb + lr + 4]);
                #pragma unroll
                for (int j = 0; j < 8; j++)
                    mma_tf32(acc[i][j], a0, a1, a2, a3, b0[j], b1[j]);
            }
        }
        __syncthreads();
    }

    #pragma unroll
    for (int i = 0; i < 2; i++) {
        int row0 = block_row + warp_m * 32 + i * 16 + lq;
        #pragma unroll
        for (int j = 0; j < 8; j++) {
            int col = warp_n * 64 + j * 8 + 2 * lr;
            if (row0 < N_NODES)
                *reinterpret_cast<float2*>(g_H1 + (size_t)row0 * NHID + col) =
                    make_float2(acc[i][j][0], acc[i][j][1]);
            if (row0 + 8 < N_NODES)
                *reinterpret_cast<float2*>(g_H1 + (size_t)(row0 + 8) * NHID + col) =
                    make_float2(acc[i][j][2], acc[i][j][3]);
        }
    }
}

// ---------------- SpMM layer 1 (CSR gather, 1 warp/row, F=128) ------------
__global__ void k_spmm1(const float* __restrict__ bias) {
    int gw = (blockIdx.x * blockDim.x + threadIdx.x) >> 5;
    int lane = threadIdx.x & 31;
    if (gw >= N_NODES) return;

    int s = g_rowptr[gw];
    int e = g_rowptr[gw + 1];
    float acc[4] = {0.f, 0.f, 0.f, 0.f};

    int i = s;
    for (; i + 1 < e; i += 2) {
        int   c0 = g_cols[i],     c1 = g_cols[i + 1];
        float v0 = g_vals[i],     v1 = g_vals[i + 1];
        const float* d0 = g_H1 + (size_t)c0 * NHID;
        const float* d1 = g_H1 + (size_t)c1 * NHID;
        float t0[4], t1[4];
        #pragma unroll
        for (int j = 0; j < 4; j++) t0[j] = d0[lane + j * 32];
        #pragma unroll
        for (int j = 0; j < 4; j++) t1[j] = d1[lane + j * 32];
        #pragma unroll
        for (int j = 0; j < 4; j++) acc[j] = fmaf(v0, t0[j], fmaf(v1, t1[j], acc[j]));
    }
    if (i < e) {
        int c = g_cols[i];
        float v = g_vals[i];
        const float* d = g_H1 + (size_t)c * NHID;
        #pragma unroll
        for (int j = 0; j < 4; j++) acc[j] = fmaf(v, d[lane + j * 32], acc[j]);
    }
    #pragma unroll
    for (int j = 0; j < 4; j++) {
        float r = acc[j] + bias[lane + j * 32];
        g_H[(size_t)gw * NHID + lane + j * 32] = fmaxf(r, 0.f);
    }
}

// ---------------- GEMM2 (register-tiled): [100000,128]x[128,40] -> g_S2 ---
// 128 rows/block; thread (tx=tid&7, ty=tid>>3) computes rows {ty+32i} x cols {5tx..5tx+4}
__global__ __launch_bounds__(256) void k_gemm2(const float* __restrict__ W2) {
    __shared__ float W2s[NHID * NCLASS];  // 20KB
    int tid = threadIdx.x;
    int rows0 = blockIdx.x * 128;

    for (int i = tid; i < NHID * NCLASS / 4; i += 256)
        reinterpret_cast<float4*>(W2s)[i] = reinterpret_cast<const float4*>(W2)[i];
    __syncthreads();

    int tx = tid & 7;
    int ty = tid >> 3;
    const int c0 = tx * 5;

    float acc[4][5];
    #pragma unroll
    for (int i = 0; i < 4; i++)
        #pragma unroll
        for (int j = 0; j < 5; j++) acc[i][j] = 0.f;

    int r[4]; bool ok[4];
    #pragma unroll
    for (int i = 0; i < 4; i++) {
        r[i] = rows0 + ty + 32 * i;
        ok[i] = r[i] < N_NODES;
    }

    for (int k4 = 0; k4 < NHID / 4; k4++) {
        float4 h[4];
        #pragma unroll
        for (int i = 0; i < 4; i++)
            h[i] = ok[i] ? reinterpret_cast<const float4*>(g_H + (size_t)r[i] * NHID)[k4]
                         : make_float4(0.f, 0.f, 0.f, 0.f);
        #pragma unroll
        for (int kk = 0; kk < 4; kk++) {
            int k = k4 * 4 + kk;
            float w[5];
            #pragma unroll
            for (int j = 0; j < 5; j++) w[j] = W2s[k * NCLASS + c0 + j];
            #pragma unroll
            for (int i = 0; i < 4; i++) {
                float hv = (kk == 0) ? h[i].x : (kk == 1) ? h[i].y : (kk == 2) ? h[i].z : h[i].w;
                #pragma unroll
                for (int j = 0; j < 5; j++) acc[i][j] = fmaf(hv, w[j], acc[i][j]);
            }
        }
    }
    #pragma unroll
    for (int i = 0; i < 4; i++)
        if (ok[i]) {
            #pragma unroll
            for (int j = 0; j < 5; j++)
                g_S2[(size_t)r[i] * NCLASS + c0 + j] = acc[i][j];
        }
}

// ---------------- SpMM layer 2 + bias + log_softmax fused (F=40) ----------
__global__ void k_spmm2ls(const float* __restrict__ bias, float* __restrict__ out) {
    int gw = (blockIdx.x * blockDim.x + threadIdx.x) >> 5;
    int lane = threadIdx.x & 31;
    if (gw >= N_NODES) return;

    int s = g_rowptr[gw];
    int e = g_rowptr[gw + 1];
    float a0 = 0.f, a1 = 0.f;

    int i = s;
    for (; i + 1 < e; i += 2) {
        int   c0 = g_cols[i],  c1 = g_cols[i + 1];
        float v0 = g_vals[i],  v1 = g_vals[i + 1];
        const float* d0 = g_S2 + (size_t)c0 * NCLASS;
        const float* d1 = g_S2 + (size_t)c1 * NCLASS;
        float p0 = d0[lane];
        float p1 = d1[lane];
        float q0 = (lane < 8) ? d0[lane + 32] : 0.f;
        float q1 = (lane < 8) ? d1[lane + 32] : 0.f;
        a0 = fmaf(v0, p0, fmaf(v1, p1, a0));
        a1 = fmaf(v0, q0, fmaf(v1, q1, a1));
    }
    if (i < e) {
        int c = g_cols[i];
        float v = g_vals[i];
        const float* d = g_S2 + (size_t)c * NCLASS;
        a0 = fmaf(v, d[lane], a0);
        if (lane < 8) a1 = fmaf(v, d[lane + 32], a1);
    }

    float v0 = a0 + bias[lane];
    float v1 = (lane < 8) ? (a1 + bias[lane + 32]) : -INFINITY;

    float m = fmaxf(v0, v1);
    #pragma unroll
    for (int off = 16; off > 0; off >>= 1)
        m = fmaxf(m, __shfl_xor_sync(0xFFFFFFFF, m, off));
    float sum = expf(v0 - m) + ((lane < 8) ? expf(v1 - m) : 0.f);
    #pragma unroll
    for (int off = 16; off > 0; off >>= 1)
        sum += __shfl_xor_sync(0xFFFFFFFF, sum, off);
    float lse = m + logf(sum);

    float* p = out + (size_t)gw * NCLASS;
    p[lane] = v0 - lse;
    if (lane < 8) p[lane + 32] = v1 - lse;
}

// ---------------- launch ----------------
extern "C" void kernel_launch(void* const* d_in, const int* in_sizes, int n_in,
                              void* d_out, int out_size) {
    const float* x    = (const float*)d_in[0];
    const void*  arow = d_in[1];
    const void*  acol = d_in[2];
    const float* aval = (const float*)d_in[3];
    const float* W1   = (const float*)d_in[4];
    const float* b1   = (const float*)d_in[5];
    const float* W2   = (const float*)d_in[6];
    const float* b2   = (const float*)d_in[7];
    float* out = (float*)d_out;

    // CSR build
    k_detect<<<1, 256>>>((const int*)arow);
    k_zero_counts<<<(N_NODES + 255) / 256, 256>>>();
    k_hist<<<(N_EDGES + 255) / 256, 256>>>(arow);
    k_scan1<<<SCAN_NBLK, SCAN_BLK>>>();
    k_scan2<<<1, 128>>>();
    k_scan3<<<(N_NODES + 255) / 256, 256>>>();
    k_scatter<<<(N_EDGES + 255) / 256, 256>>>(arow, acol, aval);

    // layer 1
    k_gemm1<<<(N_NODES + BM - 1) / BM, 256>>>(x, W1);
    k_spmm1<<<(N_NODES * 32 + 255) / 256, 256>>>(b1);

    // layer 2 (+ fused bias + log_softmax)
    k_gemm2<<<(N_NODES + 127) / 128, 256>>>(W2);
    k_spmm2ls<<<(N_NODES * 32 + 255) / 256, 256>>>(b2, out);
}